// round 10
// baseline (speedup 1.0000x reference)
#include <cuda_runtime.h>
#include <cuda_bf16.h>
#include <math.h>
#include <stdint.h>

// ---------------- problem dims ----------------
#define F_TOT 320
#define T_STEPS 20
#define B_SZ 16
#define CIN 64
#define CH 128
#define HW 1024
#define NT 2560            // total conv tiles (320 frames x 8 stripes)
#define GRID 148           // persistent CTAs

// padded plane strides (bf16 elements): [f][split][py34][px34][ci]
#define PL_PX 64
#define PL_PY 2176                     // 34*64
#define PL_S  73984                    // 34*2176
#define PL_F  221952                   // 3*PL_S

// conv smem layout
#define A_SPLIT 26112                  // 204 pixel-rows * 128B per split
#define B_BASE  78336                  // = 3 * A_SPLIT
#define B_OFF(b, s) (B_BASE + (b) * 49152 + (s) * 16384)
#define CONV_SMEM (78336 + 3 * 49152)  // 225792 B

// ---------------- device scratch ----------------
__device__ __align__(16) __nv_bfloat16 g_a[(size_t)F_TOT * PL_F];  // 142 MB
__device__ __align__(16) __nv_bfloat16 g_b[3 * 9 * 128 * 64];      // [s][r][n][ci]
__device__ float g_y[(size_t)F_TOT * CH * HW];                     // 168 MB
__device__ float g_psum[F_TOT];
__device__ int   g_pmax[F_TOT];
__device__ float g_att[F_TOT];

__device__ __forceinline__ int enc_f(float v) {
    int ix = __float_as_int(v);
    return ix >= 0 ? ix : (ix ^ 0x7fffffff);
}
__device__ __forceinline__ float dec_f(int e) {
    int ix = e >= 0 ? e : (e ^ 0x7fffffff);
    return __int_as_float(ix);
}

__device__ __forceinline__ uint32_t smem_u32(const void* p) {
    uint32_t a;
    asm("{ .reg .u64 t; cvta.to.shared.u64 t, %1; cvt.u32.u64 %0, t; }" : "=r"(a) : "l"(p));
    return a;
}

#define CP16(dst, src) \
    asm volatile("cp.async.cg.shared.global [%0], [%1], 16;" :: "r"(dst), "l"(src))
#define CP_COMMIT() asm volatile("cp.async.commit_group;" ::: "memory")
#define CP_WAIT0()  asm volatile("cp.async.wait_group 0;" ::: "memory")

#define MB_INIT(a, c) \
    asm volatile("mbarrier.init.shared.b64 [%0], %1;" :: "r"(a), "r"(c) : "memory")
#define MB_ARRIVE(a) \
    asm volatile("mbarrier.arrive.shared.b64 _, [%0];" :: "r"(a) : "memory")
#define CP_ARRIVE(a) \
    asm volatile("cp.async.mbarrier.arrive.noinc.shared.b64 [%0];" :: "r"(a) : "memory")

__device__ __forceinline__ void mb_wait(uint32_t mb, int phase) {
    asm volatile(
        "{\n\t.reg .pred P;\n\t"
        "WL%=:\n\t"
        "mbarrier.try_wait.parity.shared.b64 P, [%0], %1;\n\t"
        "@!P bra WL%=;\n\t}"
        :: "r"(mb), "r"((uint32_t)phase) : "memory");
}

#define LDSM4(r0, r1, r2, r3, addr)                                              \
    asm volatile("ldmatrix.sync.aligned.m8n8.x4.shared.b16 {%0,%1,%2,%3}, [%4];" \
                 : "=r"(r0), "=r"(r1), "=r"(r2), "=r"(r3) : "r"(addr))

#define MMA16816(D, A, B0, B1)                                                 \
    asm volatile("mma.sync.aligned.m16n8k16.row.col.f32.bf16.bf16.f32 "        \
                 "{%0,%1,%2,%3}, {%4,%5,%6,%7}, {%8,%9}, {%0,%1,%2,%3};"       \
                 : "+f"(D[0]), "+f"(D[1]), "+f"(D[2]), "+f"(D[3])              \
                 : "r"(A[0]), "r"(A[1]), "r"(A[2]), "r"(A[3]), "r"(B0), "r"(B1))

// ---------------- kernel 1: reset pools ----------------
__global__ void init_kernel() {
    int i = blockIdx.x * blockDim.x + threadIdx.x;
    if (i < F_TOT) {
        g_psum[i] = 0.f;
        g_pmax[i] = 0x80000000;
    }
}

// ---------------- kernel 2: weight split-3 -> g_b[s][r][n][ci] ----------------
__global__ void prep_w_kernel(const float* __restrict__ w) {
    int i = blockIdx.x * blockDim.x + threadIdx.x;
    if (i >= 9 * 128 * 64) return;
    int r = i >> 13;
    int rem = i & 8191;
    int n = rem >> 6;
    int ci = rem & 63;
    float x = w[n * 576 + ci * 9 + r];
    __nv_bfloat16 b0 = __float2bfloat16(x);
    float r1 = x - __bfloat162float(b0);
    __nv_bfloat16 b1 = __float2bfloat16(r1);
    float r2 = r1 - __bfloat162float(b1);
    __nv_bfloat16 b2 = __float2bfloat16(r2);
    int off = r * 8192 + n * 64 + ci;
    g_b[off] = b0;
    g_b[73728 + off] = b1;
    g_b[2 * 73728 + off] = b2;
}

// ---------------- kernel 3: data split-3 -> zero-padded 34x34 planes ----------------
__global__ __launch_bounds__(256) void prep_data_kernel(const float* __restrict__ data) {
    __shared__ float srow[64][33];
    const int py34 = blockIdx.x;
    const int f = blockIdx.y;
    const int tid = threadIdx.x;
    const int py = py34 - 1;
    const bool rv = (unsigned)py < 32u;

    for (int e = tid; e < 2048; e += 256) {
        int ci = e >> 5, px = e & 31;
        srow[ci][px] = rv ? __ldg(&data[(size_t)f * 65536 + ci * 1024 + py * 32 + px]) : 0.f;
    }
    __syncthreads();

    const int ci = tid & 63;
    const int pg = tid >> 6;
    const size_t rowbase = (size_t)f * PL_F + (size_t)py34 * PL_PY;
#pragma unroll
    for (int it = 0; it < 9; it++) {
        int px34 = pg + it * 4;
        if (px34 >= 34) break;
        int px = px34 - 1;
        float x = (rv && (unsigned)px < 32u) ? srow[ci][px] : 0.f;
        __nv_bfloat16 b0 = __float2bfloat16(x);
        float r1 = x - __bfloat162float(b0);
        __nv_bfloat16 b1 = __float2bfloat16(r1);
        float r2 = r1 - __bfloat162float(b1);
        __nv_bfloat16 b2 = __float2bfloat16(r2);
        size_t o = rowbase + px34 * PL_PX + ci;
        g_a[o] = b0;
        g_a[o + PL_S] = b1;
        g_a[o + 2 * PL_S] = b2;
    }
}

// ---------------- kernel 4: persistent conv, mbarrier B ring ----------------
// grid = 148, 512 threads (16 warps)
// smem: [0, 78336) A tile (also epilogue sy); [78336, 225792) B ring (3 x 48KB)
__global__ __launch_bounds__(512, 1) void conv_kernel(const float* __restrict__ bias) {
    extern __shared__ char smem[];
    const uint32_t sb = smem_u32(smem);
    __shared__ __align__(8) unsigned long long mbar[6];   // full[0..2], empty[0..2]
    __shared__ float red_s[16], red_m[16];

    const int tid = threadIdx.x;
    const int lane = tid & 31;
    const int wid = tid >> 5;
    const int warp_m = wid >> 2;
    const int warp_n = wid & 3;

    const uint32_t mb_full0 = smem_u32(&mbar[0]);
    const uint32_t mb_empt0 = smem_u32(&mbar[3]);

    // B staging map: row = tid>>2 (n 0..127), quarter = tid&3
    const int srow_i = tid >> 2;
    const int q = tid & 3;
    const uint32_t stgB_row = srow_i * 128;
    const uint32_t stgB_xor = (srow_i & 7) << 4;
    const uint32_t stgB_c0 = q * 32;

    // ldmatrix lane roles
    const uint32_t pbase = warp_m * 34 + (lane & 15);
    const uint32_t cA = (lane >> 4) * 16;
    const uint32_t rowB_off = (warp_n * 32 + (lane & 7) + ((lane >> 4) & 1) * 8) * 128;
    const uint32_t cB = ((lane >> 3) & 1) * 16;
    const uint32_t xorB = (lane & 7) << 4;

    float acc_m[2][4][4];
    float acc_c[2][4][4];

    auto stageA = [&](int f_, int row0_) {
        const size_t fb = (size_t)f_ * PL_F;
        for (int e = tid; e < 4896; e += 512) {
            int s = e / 1632;
            int rem = e - s * 1632;
            int p = rem >> 3;
            int j = rem & 7;
            int prow = p / 34;
            int ppx = p - prow * 34;
            const __nv_bfloat16* src = g_a + fb + (size_t)s * PL_S +
                (size_t)(row0_ + prow) * PL_PY + ppx * PL_PX + j * 8;
            uint32_t dst = sb + s * A_SPLIT + p * 128 + ((j * 16) ^ ((p & 7) << 4));
            CP16(dst, src);
        }
    };

    auto stageB = [&](int r, int b) {
        const size_t bbase = (size_t)r * 8192 + (size_t)srow_i * 64 + q * 16;
#pragma unroll
        for (int s = 0; s < 3; s++) {
            const __nv_bfloat16* pb = g_b + bbase + (size_t)s * 73728;
            uint32_t db = sb + B_OFF(b, s) + stgB_row;
#pragma unroll
            for (int j = 0; j < 2; j++) {
                uint32_t sw = (stgB_c0 + j * 16) ^ stgB_xor;
                CP16(db + sw, pb + j * 8);
            }
        }
    };

    auto ldA = [&](int s, int droff, int k, uint32_t (&Af)[2][4]) {
#pragma unroll
        for (int mt = 0; mt < 2; mt++) {
            uint32_t p = pbase + droff + mt * 16;
            uint32_t addr = sb + s * A_SPLIT + p * 128 + ((cA + k * 32) ^ ((p & 7) << 4));
            LDSM4(Af[mt][0], Af[mt][1], Af[mt][2], Af[mt][3], addr);
        }
    };
    auto ldB = [&](uint32_t bb, int k, uint32_t (&Bf)[2][4]) {
#pragma unroll
        for (int bh = 0; bh < 2; bh++) {
            uint32_t addr = bb + rowB_off + bh * 2048 + ((cB + k * 32) ^ xorB);
            LDSM4(Bf[bh][0], Bf[bh][1], Bf[bh][2], Bf[bh][3], addr);
        }
    };
    auto mma8 = [&](uint32_t (&Af)[2][4], uint32_t (&Bf)[2][4], float (&acc)[2][4][4]) {
#pragma unroll
        for (int mt = 0; mt < 2; mt++)
#pragma unroll
            for (int nt = 0; nt < 4; nt++)
                MMA16816(acc[mt][nt], Af[mt], Bf[nt >> 1][(nt & 1) * 2],
                         Bf[nt >> 1][(nt & 1) * 2 + 1]);
    };
    auto compute = [&](int b, int droff) {
        const uint32_t b0 = sb + B_OFF(b, 0), b1 = sb + B_OFF(b, 1), b2 = sb + B_OFF(b, 2);
#pragma unroll
        for (int k = 0; k < 4; k++) {
            uint32_t Af0[2][4], Afx[2][4], Bf0[2][4], Bfx[2][4];
            ldA(0, droff, k, Af0);
            ldA(1, droff, k, Afx);
            ldB(b0, k, Bf0);
            ldB(b1, k, Bfx);
            mma8(Af0, Bf0, acc_m);   // main A0B0
            mma8(Af0, Bfx, acc_c);   // A0B1
            mma8(Afx, Bf0, acc_c);   // A1B0
            mma8(Afx, Bfx, acc_c);   // A1B1
            ldB(b2, k, Bfx);
            mma8(Af0, Bfx, acc_c);   // A0B2
            ldA(2, droff, k, Afx);
            mma8(Afx, Bf0, acc_c);   // A2B0
        }
    };

    // ---- barrier init + initial phase prime ----
    if (tid == 0) {
#pragma unroll
        for (int i = 0; i < 6; i++) MB_INIT(smem_u32(&mbar[i]), 512);
    }
    __syncthreads();
#pragma unroll
    for (int i = 0; i < 3; i++) MB_ARRIVE(mb_empt0 + i * 8);   // empties complete phase 0

    int fph[3] = {0, 0, 0};
    int eph[3] = {0, 0, 0};

    // ---- prologue: first tile A + B(0->buf0), B(1->buf1) ----
    {
        int t0 = blockIdx.x;
        stageA(t0 >> 3, (t0 & 7) * 4);
        CP_COMMIT();
        mb_wait(mb_empt0 + 0, eph[0]); eph[0] ^= 1;
        stageB(0, 0);
        CP_ARRIVE(mb_full0 + 0);
        mb_wait(mb_empt0 + 8, eph[1]); eph[1] ^= 1;
        stageB(1, 1);
        CP_ARRIVE(mb_full0 + 8);
    }

    for (int tix = blockIdx.x; tix < NT; tix += GRID) {
        const int f = tix >> 3;
        const int row0 = (tix & 7) * 4;

        CP_WAIT0();              // this thread's A cps done
        __syncthreads();         // all threads' A visible; prev epilogue done

#pragma unroll
        for (int i = 0; i < 2; i++)
#pragma unroll
            for (int j = 0; j < 4; j++)
#pragma unroll
                for (int d = 0; d < 4; d++) {
                    acc_m[i][j][d] = 0.f;
                    acc_c[i][j][d] = 0.f;
                }

#pragma unroll
        for (int r = 0; r < 9; r++) {
            if (r + 2 <= 8) {
                const int nb = (r + 2) % 3;
                mb_wait(mb_empt0 + nb * 8, eph[nb]); eph[nb] ^= 1;
                stageB(r + 2, nb);
                CP_ARRIVE(mb_full0 + nb * 8);
            }
            const int buf = r % 3;
            mb_wait(mb_full0 + buf * 8, fph[buf]); fph[buf] ^= 1;
            compute(buf, (r / 3) * 34 + (r % 3));
            MB_ARRIVE(mb_empt0 + buf * 8);
        }

        // ---- epilogue: sy transpose in (dead) A region ----
        __syncthreads();          // all computes done; A region free
        float* sy = (float*)smem; // [128][129] fp32, 66KB
#pragma unroll
        for (int mt = 0; mt < 2; mt++) {
            int m0 = warp_m * 32 + mt * 16 + (lane >> 2);
#pragma unroll
            for (int nt = 0; nt < 4; nt++) {
                int n0 = warp_n * 32 + nt * 8 + 2 * (lane & 3);
                sy[m0 * 129 + n0]           = acc_m[mt][nt][0] + acc_c[mt][nt][0];
                sy[m0 * 129 + n0 + 1]       = acc_m[mt][nt][1] + acc_c[mt][nt][1];
                sy[(m0 + 8) * 129 + n0]     = acc_m[mt][nt][2] + acc_c[mt][nt][2];
                sy[(m0 + 8) * 129 + n0 + 1] = acc_m[mt][nt][3] + acc_c[mt][nt][3];
            }
        }
        __syncthreads();

        const int pix = tid >> 2;
        const int n0 = (tid & 3) * 32;
        float lsum = 0.f, lmax = -1e30f;
        const size_t yb = (size_t)f * (CH * HW) + row0 * 32 + pix;
#pragma unroll 8
        for (int j = 0; j < 32; j++) {
            int n = n0 + j;
            float v = sy[pix * 129 + n] + __ldg(&bias[n]);
            g_y[yb + (size_t)n * HW] = v;
            lsum += v;
            lmax = fmaxf(lmax, v);
        }

#pragma unroll
        for (int off = 16; off; off >>= 1) {
            lsum += __shfl_down_sync(0xffffffff, lsum, off);
            lmax = fmaxf(lmax, __shfl_down_sync(0xffffffff, lmax, off));
        }
        if (lane == 0) {
            red_s[wid] = lsum;
            red_m[wid] = lmax;
        }
        __syncthreads();          // sy fully consumed by all threads

        const int ntix = tix + GRID;
        if (ntix < NT) {
            stageA(ntix >> 3, (ntix & 7) * 4);   // overwrites sy (safe post-sync)
            CP_COMMIT();
            mb_wait(mb_empt0 + 0, eph[0]); eph[0] ^= 1;
            stageB(0, 0);
            CP_ARRIVE(mb_full0 + 0);
            mb_wait(mb_empt0 + 8, eph[1]); eph[1] ^= 1;
            stageB(1, 1);
            CP_ARRIVE(mb_full0 + 8);
        }
        if (tid == 0) {
            float s = 0.f, mx = -1e30f;
#pragma unroll
            for (int w = 0; w < 16; w++) {
                s += red_s[w];
                mx = fmaxf(mx, red_m[w]);
            }
            atomicAdd(&g_psum[f], s);
            atomicMax(&g_pmax[f], enc_f(mx));
        }
    }
}

// ---------------- kernel 5: temporal attention ----------------
__global__ void att_kernel(const float* __restrict__ w1, const float* __restrict__ w2) {
    int tid = threadIdx.x;
    if (tid >= F_TOT) return;
    int b = tid / T_STEPS;
    int t = tid - b * T_STEPS;
    float avgv[T_STEPS], mxv[T_STEPS];
#pragma unroll
    for (int tt = 0; tt < T_STEPS; tt++) {
        avgv[tt] = g_psum[b * T_STEPS + tt] * (1.f / (float)(CH * HW));
        mxv[tt] = dec_f(g_pmax[b * T_STEPS + tt]);
    }
    float o = 0.f;
#pragma unroll
    for (int j = 0; j < 5; j++) {
        float ha = 0.f, hm = 0.f;
#pragma unroll
        for (int tt = 0; tt < T_STEPS; tt++) {
            float w = w1[j * T_STEPS + tt];
            ha = fmaf(avgv[tt], w, ha);
            hm = fmaf(mxv[tt], w, hm);
        }
        ha = fmaxf(ha, 0.f);
        hm = fmaxf(hm, 0.f);
        o = fmaf(ha + hm, w2[t * 5 + j], o);
    }
    g_att[tid] = 1.f / (1.f + expf(-o));
}

// ---------------- kernel 6: LIF ----------------
__global__ __launch_bounds__(256) void lif_kernel(float* __restrict__ out) {
    int idx = blockIdx.x * blockDim.x + threadIdx.x;
    int b = idx >> 17;
    int r = idx & 131071;
    float h = 0.f;
#pragma unroll
    for (int t = 0; t < T_STEPS; t++) {
        int f = b * T_STEPS + t;
        size_t off = (size_t)f * (CH * HW) + r;
        float v = g_y[off] * g_att[f];
        float u = fmaf(h, 0.3f, v);
        float s = (u >= 0.6f) ? 1.f : 0.f;
        out[off] = s;
        h = u * (1.f - s);
    }
}

// ---------------- launch ----------------
extern "C" void kernel_launch(void* const* d_in, const int* in_sizes, int n_in,
                              void* d_out, int out_size) {
    const float* data   = (const float*)d_in[0];
    const float* conv_w = (const float*)d_in[1];
    const float* conv_b = (const float*)d_in[2];
    const float* mlp_w1 = (const float*)d_in[3];
    const float* mlp_w2 = (const float*)d_in[4];
    float* out = (float*)d_out;

    static int smem_set = 0;
    if (!smem_set) {
        cudaFuncSetAttribute(conv_kernel, cudaFuncAttributeMaxDynamicSharedMemorySize,
                             CONV_SMEM);
        smem_set = 1;
    }

    init_kernel<<<(F_TOT + 255) / 256, 256>>>();
    prep_w_kernel<<<(9 * 128 * 64 + 255) / 256, 256>>>(conv_w);
    prep_data_kernel<<<dim3(34, F_TOT), 256>>>(data);
    conv_kernel<<<GRID, 512, CONV_SMEM>>>(conv_b);
    att_kernel<<<1, F_TOT>>>(mlp_w1, mlp_w2);
    lif_kernel<<<(B_SZ * CH * HW) / 256, 256>>>(out);
}

// round 11
// speedup vs baseline: 1.1278x; 1.1278x over previous
#include <cuda_runtime.h>
#include <cuda_bf16.h>
#include <math.h>
#include <stdint.h>

// ---------------- problem dims ----------------
#define F_TOT 320
#define T_STEPS 20
#define B_SZ 16
#define CIN 64
#define CH 128
#define HW 1024
#define NT 2560            // total conv tiles (320 frames x 8 stripes)
#define GRID 148           // persistent CTAs

// padded plane strides (bf16 elements): [f][split][py34][px34][ci]
#define PL_PX 64
#define PL_PY 2176                     // 34*64
#define PL_S  73984                    // 34*2176
#define PL_F  221952                   // 3*PL_S

// conv smem layout
#define A_SPLIT 26112                  // 204 pixel-rows * 128B per split
#define B_BASE  78336                  // = 3 * A_SPLIT
#define B_OFF(b, s) (B_BASE + (b) * 49152 + (s) * 16384)
#define CONV_SMEM (78336 + 98304)      // 176640 B

// ---------------- device scratch ----------------
__device__ __align__(16) __nv_bfloat16 g_a[(size_t)F_TOT * PL_F];  // 142 MB
__device__ __align__(16) __nv_bfloat16 g_b[3 * 9 * 128 * 64];      // [s][r][n][ci]
__device__ float g_y[(size_t)F_TOT * CH * HW];                     // 168 MB
__device__ float g_psum[F_TOT];
__device__ int   g_pmax[F_TOT];
__device__ float g_att[F_TOT];

__device__ __forceinline__ int enc_f(float v) {
    int ix = __float_as_int(v);
    return ix >= 0 ? ix : (ix ^ 0x7fffffff);
}
__device__ __forceinline__ float dec_f(int e) {
    int ix = e >= 0 ? e : (e ^ 0x7fffffff);
    return __int_as_float(ix);
}

__device__ __forceinline__ uint32_t smem_u32(const void* p) {
    uint32_t a;
    asm("{ .reg .u64 t; cvta.to.shared.u64 t, %1; cvt.u32.u64 %0, t; }" : "=r"(a) : "l"(p));
    return a;
}

#define CP16(dst, src) \
    asm volatile("cp.async.cg.shared.global [%0], [%1], 16;" :: "r"(dst), "l"(src))
#define CP_COMMIT() asm volatile("cp.async.commit_group;" ::: "memory")
#define CP_WAIT0()  asm volatile("cp.async.wait_group 0;" ::: "memory")

#define LDSM4(r0, r1, r2, r3, addr)                                              \
    asm volatile("ldmatrix.sync.aligned.m8n8.x4.shared.b16 {%0,%1,%2,%3}, [%4];" \
                 : "=r"(r0), "=r"(r1), "=r"(r2), "=r"(r3) : "r"(addr))

#define MMA16816(D, A, B0, B1)                                                 \
    asm volatile("mma.sync.aligned.m16n8k16.row.col.f32.bf16.bf16.f32 "        \
                 "{%0,%1,%2,%3}, {%4,%5,%6,%7}, {%8,%9}, {%0,%1,%2,%3};"       \
                 : "+f"(D[0]), "+f"(D[1]), "+f"(D[2]), "+f"(D[3])              \
                 : "r"(A[0]), "r"(A[1]), "r"(A[2]), "r"(A[3]), "r"(B0), "r"(B1))

// ---------------- kernel 1: reset pools ----------------
__global__ void init_kernel() {
    int i = blockIdx.x * blockDim.x + threadIdx.x;
    if (i < F_TOT) {
        g_psum[i] = 0.f;
        g_pmax[i] = 0x80000000;
    }
}

// ---------------- kernel 2: weight split-3 -> g_b[s][r][n][ci] ----------------
__global__ void prep_w_kernel(const float* __restrict__ w) {
    int i = blockIdx.x * blockDim.x + threadIdx.x;
    if (i >= 9 * 128 * 64) return;
    int r = i >> 13;
    int rem = i & 8191;
    int n = rem >> 6;
    int ci = rem & 63;
    float x = w[n * 576 + ci * 9 + r];
    __nv_bfloat16 b0 = __float2bfloat16(x);
    float r1 = x - __bfloat162float(b0);
    __nv_bfloat16 b1 = __float2bfloat16(r1);
    float r2 = r1 - __bfloat162float(b1);
    __nv_bfloat16 b2 = __float2bfloat16(r2);
    int off = r * 8192 + n * 64 + ci;
    g_b[off] = b0;
    g_b[73728 + off] = b1;
    g_b[2 * 73728 + off] = b2;
}

// ---------------- kernel 3: data split-3 -> zero-padded 34x34 planes ----------------
__global__ __launch_bounds__(256) void prep_data_kernel(const float* __restrict__ data) {
    __shared__ float srow[64][33];
    const int py34 = blockIdx.x;
    const int f = blockIdx.y;
    const int tid = threadIdx.x;
    const int py = py34 - 1;
    const bool rv = (unsigned)py < 32u;

    for (int e = tid; e < 2048; e += 256) {
        int ci = e >> 5, px = e & 31;
        srow[ci][px] = rv ? __ldg(&data[(size_t)f * 65536 + ci * 1024 + py * 32 + px]) : 0.f;
    }
    __syncthreads();

    const int ci = tid & 63;
    const int pg = tid >> 6;
    const size_t rowbase = (size_t)f * PL_F + (size_t)py34 * PL_PY;
#pragma unroll
    for (int it = 0; it < 9; it++) {
        int px34 = pg + it * 4;
        if (px34 >= 34) break;
        int px = px34 - 1;
        float x = (rv && (unsigned)px < 32u) ? srow[ci][px] : 0.f;
        __nv_bfloat16 b0 = __float2bfloat16(x);
        float r1 = x - __bfloat162float(b0);
        __nv_bfloat16 b1 = __float2bfloat16(r1);
        float r2 = r1 - __bfloat162float(b1);
        __nv_bfloat16 b2 = __float2bfloat16(r2);
        size_t o = rowbase + px34 * PL_PX + ci;
        g_a[o] = b0;
        g_a[o + PL_S] = b1;
        g_a[o + 2 * PL_S] = b2;
    }
}

// ---------------- kernel 4: persistent mma.sync conv, A-resident, direct epilogue ----------------
// grid = 148, 512 threads (16 warps)
// smem: [0, 78336) A tile; [78336, 176640) B double buffer
__global__ __launch_bounds__(512, 1) void conv_kernel(const float* __restrict__ bias) {
    extern __shared__ char smem[];
    const uint32_t sb = smem_u32(smem);
    __shared__ float red_s[16], red_m[16];

    const int tid = threadIdx.x;
    const int lane = tid & 31;
    const int wid = tid >> 5;
    const int warp_m = wid >> 2;      // 0..3 (32 pixels each)
    const int warp_n = wid & 3;       // 0..3 (32 channels each)

    // B staging map: row = tid>>2 (n 0..127), quarter = tid&3
    const int srow_i = tid >> 2;
    const int q = tid & 3;
    const uint32_t stgB_row = srow_i * 128;
    const uint32_t stgB_xor = (srow_i & 7) << 4;
    const uint32_t stgB_c0 = q * 32;

    // ldmatrix lane roles
    const uint32_t pbase = warp_m * 34 + (lane & 15);   // A pixel-row within padded tile
    const uint32_t cA = (lane >> 4) * 16;
    const uint32_t rowB_off = (warp_n * 32 + (lane & 7) + ((lane >> 4) & 1) * 8) * 128;
    const uint32_t cB = ((lane >> 3) & 1) * 16;
    const uint32_t xorB = (lane & 7) << 4;

    float acc_m[2][4][4];
    float acc_c[2][4][4];

    auto stageA = [&](int f_, int row0_) {
        const size_t fb = (size_t)f_ * PL_F;
        for (int e = tid; e < 4896; e += 512) {
            int s = e / 1632;
            int rem = e - s * 1632;
            int p = rem >> 3;            // 0..203 pixel-row
            int j = rem & 7;             // 16B segment
            int prow = p / 34;
            int ppx = p - prow * 34;
            const __nv_bfloat16* src = g_a + fb + (size_t)s * PL_S +
                (size_t)(row0_ + prow) * PL_PY + ppx * PL_PX + j * 8;
            uint32_t dst = sb + s * A_SPLIT + p * 128 + ((j * 16) ^ ((p & 7) << 4));
            CP16(dst, src);
        }
    };

    auto stageB = [&](int r, int b) {
        const size_t bbase = (size_t)r * 8192 + (size_t)srow_i * 64 + q * 16;
#pragma unroll
        for (int s = 0; s < 3; s++) {
            const __nv_bfloat16* pb = g_b + bbase + (size_t)s * 73728;
            uint32_t db = sb + B_OFF(b, s) + stgB_row;
#pragma unroll
            for (int j = 0; j < 2; j++) {
                uint32_t sw = (stgB_c0 + j * 16) ^ stgB_xor;
                CP16(db + sw, pb + j * 8);
            }
        }
    };

    auto ldA = [&](int s, int droff, int k, uint32_t (&Af)[2][4]) {
#pragma unroll
        for (int mt = 0; mt < 2; mt++) {
            uint32_t p = pbase + droff + mt * 16;
            uint32_t addr = sb + s * A_SPLIT + p * 128 + ((cA + k * 32) ^ ((p & 7) << 4));
            LDSM4(Af[mt][0], Af[mt][1], Af[mt][2], Af[mt][3], addr);
        }
    };
    auto ldB = [&](uint32_t bb, int k, uint32_t (&Bf)[2][4]) {
#pragma unroll
        for (int bh = 0; bh < 2; bh++) {
            uint32_t addr = bb + rowB_off + bh * 2048 + ((cB + k * 32) ^ xorB);
            LDSM4(Bf[bh][0], Bf[bh][1], Bf[bh][2], Bf[bh][3], addr);
        }
    };
    auto mma8 = [&](uint32_t (&Af)[2][4], uint32_t (&Bf)[2][4], float (&acc)[2][4][4]) {
#pragma unroll
        for (int mt = 0; mt < 2; mt++)
#pragma unroll
            for (int nt = 0; nt < 4; nt++)
                MMA16816(acc[mt][nt], Af[mt], Bf[nt >> 1][(nt & 1) * 2],
                         Bf[nt >> 1][(nt & 1) * 2 + 1]);
    };
    auto compute = [&](int b, int droff) {
        const uint32_t b0 = sb + B_OFF(b, 0), b1 = sb + B_OFF(b, 1), b2 = sb + B_OFF(b, 2);
#pragma unroll
        for (int k = 0; k < 4; k++) {
            uint32_t Af0[2][4], Afx[2][4], Bf0[2][4], Bfx[2][4];
            ldA(0, droff, k, Af0);
            ldA(1, droff, k, Afx);
            ldB(b0, k, Bf0);
            ldB(b1, k, Bfx);
            mma8(Af0, Bf0, acc_m);   // main A0B0
            mma8(Af0, Bfx, acc_c);   // A0B1
            mma8(Afx, Bf0, acc_c);   // A1B0
            mma8(Afx, Bfx, acc_c);   // A1B1
            ldB(b2, k, Bfx);
            mma8(Af0, Bfx, acc_c);   // A0B2
            ldA(2, droff, k, Afx);
            mma8(Afx, Bf0, acc_c);   // A2B0
        }
    };

    // ---- prologue: A + B(r=0) for first tile ----
    int buf = 0;
    {
        int t0 = blockIdx.x;
        stageA(t0 >> 3, (t0 & 7) * 4);
        stageB(0, 0);
        CP_COMMIT();
    }

    for (int tix = blockIdx.x; tix < NT; tix += GRID) {
        const int f = tix >> 3;
        const int row0 = (tix & 7) * 4;

#pragma unroll
        for (int i = 0; i < 2; i++)
#pragma unroll
            for (int j = 0; j < 4; j++)
#pragma unroll
                for (int d = 0; d < 4; d++) {
                    acc_m[i][j][d] = 0.f;
                    acc_c[i][j][d] = 0.f;
                }

        for (int r = 0; r < 9; r++) {
            CP_WAIT0();
            __syncthreads();          // publishes staged data; fences prev compute
            if (r < 8) {
                stageB(r + 1, buf ^ 1);
                CP_COMMIT();
            }
            compute(buf, (r / 3) * 34 + (r % 3));
            buf ^= 1;
        }

        // ---- prefetch next tile (A + B(r=0)) right after compute finishes ----
        __syncthreads();              // all compute done; A and B regions free
        const int ntix = tix + GRID;
        if (ntix < NT) {
            stageA(ntix >> 3, (ntix & 7) * 4);
            stageB(0, buf);
            CP_COMMIT();
        }

        // ---- direct-register epilogue: bias + store + pool (no transpose) ----
        float lsum = 0.f, lmax = -1e30f;
        const size_t yb = (size_t)f * (CH * HW) + (size_t)row0 * 32;
#pragma unroll
        for (int nt = 0; nt < 4; nt++) {
            const int n0 = warp_n * 32 + nt * 8 + 2 * (lane & 3);
            const float bv0 = __ldg(&bias[n0]);
            const float bv1 = __ldg(&bias[n0 + 1]);
            const size_t cb0 = yb + (size_t)n0 * HW;
            const size_t cb1 = yb + (size_t)(n0 + 1) * HW;
#pragma unroll
            for (int mt = 0; mt < 2; mt++) {
                const int m0 = warp_m * 32 + mt * 16 + (lane >> 2);
                float v0 = acc_m[mt][nt][0] + acc_c[mt][nt][0] + bv0;
                float v1 = acc_m[mt][nt][1] + acc_c[mt][nt][1] + bv1;
                float v2 = acc_m[mt][nt][2] + acc_c[mt][nt][2] + bv0;
                float v3 = acc_m[mt][nt][3] + acc_c[mt][nt][3] + bv1;
                g_y[cb0 + m0]     = v0;
                g_y[cb1 + m0]     = v1;
                g_y[cb0 + m0 + 8] = v2;
                g_y[cb1 + m0 + 8] = v3;
                lsum += v0 + v1 + v2 + v3;
                lmax = fmaxf(lmax, fmaxf(fmaxf(v0, v1), fmaxf(v2, v3)));
            }
        }

#pragma unroll
        for (int off = 16; off; off >>= 1) {
            lsum += __shfl_down_sync(0xffffffff, lsum, off);
            lmax = fmaxf(lmax, __shfl_down_sync(0xffffffff, lmax, off));
        }
        if (lane == 0) {
            red_s[wid] = lsum;
            red_m[wid] = lmax;
        }
        __syncthreads();
        if (tid == 0) {
            float s = 0.f, mx = -1e30f;
#pragma unroll
            for (int w = 0; w < 16; w++) {
                s += red_s[w];
                mx = fmaxf(mx, red_m[w]);
            }
            atomicAdd(&g_psum[f], s);
            atomicMax(&g_pmax[f], enc_f(mx));
        }
    }
}

// ---------------- kernel 5: temporal attention ----------------
__global__ void att_kernel(const float* __restrict__ w1, const float* __restrict__ w2) {
    int tid = threadIdx.x;
    if (tid >= F_TOT) return;
    int b = tid / T_STEPS;
    int t = tid - b * T_STEPS;
    float avgv[T_STEPS], mxv[T_STEPS];
#pragma unroll
    for (int tt = 0; tt < T_STEPS; tt++) {
        avgv[tt] = g_psum[b * T_STEPS + tt] * (1.f / (float)(CH * HW));
        mxv[tt] = dec_f(g_pmax[b * T_STEPS + tt]);
    }
    float o = 0.f;
#pragma unroll
    for (int j = 0; j < 5; j++) {
        float ha = 0.f, hm = 0.f;
#pragma unroll
        for (int tt = 0; tt < T_STEPS; tt++) {
            float w = w1[j * T_STEPS + tt];
            ha = fmaf(avgv[tt], w, ha);
            hm = fmaf(mxv[tt], w, hm);
        }
        ha = fmaxf(ha, 0.f);
        hm = fmaxf(hm, 0.f);
        o = fmaf(ha + hm, w2[t * 5 + j], o);
    }
    g_att[tid] = 1.f / (1.f + expf(-o));
}

// ---------------- kernel 6: LIF ----------------
__global__ __launch_bounds__(256) void lif_kernel(float* __restrict__ out) {
    int idx = blockIdx.x * blockDim.x + threadIdx.x;
    int b = idx >> 17;
    int r = idx & 131071;
    float h = 0.f;
#pragma unroll
    for (int t = 0; t < T_STEPS; t++) {
        int f = b * T_STEPS + t;
        size_t off = (size_t)f * (CH * HW) + r;
        float v = g_y[off] * g_att[f];
        float u = fmaf(h, 0.3f, v);
        float s = (u >= 0.6f) ? 1.f : 0.f;
        out[off] = s;
        h = u * (1.f - s);
    }
}

// ---------------- launch ----------------
extern "C" void kernel_launch(void* const* d_in, const int* in_sizes, int n_in,
                              void* d_out, int out_size) {
    const float* data   = (const float*)d_in[0];
    const float* conv_w = (const float*)d_in[1];
    const float* conv_b = (const float*)d_in[2];
    const float* mlp_w1 = (const float*)d_in[3];
    const float* mlp_w2 = (const float*)d_in[4];
    float* out = (float*)d_out;

    static int smem_set = 0;
    if (!smem_set) {
        cudaFuncSetAttribute(conv_kernel, cudaFuncAttributeMaxDynamicSharedMemorySize,
                             CONV_SMEM);
        smem_set = 1;
    }

    init_kernel<<<(F_TOT + 255) / 256, 256>>>();
    prep_w_kernel<<<(9 * 128 * 64 + 255) / 256, 256>>>(conv_w);
    prep_data_kernel<<<dim3(34, F_TOT), 256>>>(data);
    conv_kernel<<<GRID, 512, CONV_SMEM>>>(conv_b);
    att_kernel<<<1, F_TOT>>>(mlp_w1, mlp_w2);
    lif_kernel<<<(B_SZ * CH * HW) / 256, 256>>>(out);
}